// round 16
// baseline (speedup 1.0000x reference)
#include <cuda_runtime.h>
#include <cuda_bf16.h>
#include <cstdint>
#include <cstddef>
#include <math.h>

#define BATCH 64
#define IDIM  512
#define HDIM  1024
#define GDIM  4096
#define TLEN  256
#define ODIM  512
#define M1    (TLEN*BATCH)
#define NCTA  128
#define BG    32
#define HPAD  1032

// lstm SMEM byte offsets (triple-buffered A chunks)
#define SM_WS    0                         // 64*HPAD*2 = 132096
#define SM_ABUF  132096                    // 4 kh * 3 bufs * 4608B = 55296
#define SM_GS    (132096 + 55296)          // Gs [4][32][68] f32 = 34816
#define SM_CS    (SM_GS + 34816)           // cs [32][16] f32
#define LSTM_SMEM (SM_CS + 2048)           // 224256

// 2-stage pipelined bf16 GEMM (x_proj, 128x128)
#define XA_STAGE 18432
#define XB_STAGE 18432
#define X_BS_OFF (2*XA_STAGE + 2*XB_STAGE)
#define XGEMM_SMEM (X_BS_OFF + 512)

// 2-stage pipelined tf32 GEMM (head, 128x128)
#define GA_STAGE 18432
#define GB_STAGE 18432
#define G_BS_OFF (2*GA_STAGE + 2*GB_STAGE)
#define GEMM_SMEM (G_BS_OFF + 512)

__device__ float g_xt[(size_t)M1 * ODIM];
__device__ __nv_bfloat16 g_xtb[(size_t)M1 * IDIM];
__device__ __nv_bfloat16 g_wihb[(size_t)GDIM * IDIM];
__device__ float g_xproj[(size_t)M1 * GDIM];
__device__ float g_chist[(size_t)M1 * HDIM];
__device__ __nv_bfloat16 g_hb[2][BATCH * HDIM];
__device__ float g_bias[GDIM];
__device__ unsigned g_cnt[2 * (TLEN + 1)];

__device__ __forceinline__ float to_tf32(float x) {
    unsigned u; asm("cvt.rna.tf32.f32 %0, %1;" : "=r"(u) : "f"(x));
    return __uint_as_float(u);
}

__device__ __forceinline__ void mma_tf32(float c[4], const float a[4], const float b[2]) {
    asm volatile(
        "mma.sync.aligned.m16n8k8.row.col.f32.tf32.tf32.f32 "
        "{%0,%1,%2,%3}, {%4,%5,%6,%7}, {%8,%9}, {%0,%1,%2,%3};"
        : "+f"(c[0]), "+f"(c[1]), "+f"(c[2]), "+f"(c[3])
        : "r"(__float_as_uint(a[0])), "r"(__float_as_uint(a[1])),
          "r"(__float_as_uint(a[2])), "r"(__float_as_uint(a[3])),
          "r"(__float_as_uint(b[0])), "r"(__float_as_uint(b[1])));
}

__device__ __forceinline__ void mma_bf16(float c[4], const unsigned a[4], const unsigned b[2]) {
    asm volatile(
        "mma.sync.aligned.m16n8k16.row.col.f32.bf16.bf16.f32 "
        "{%0,%1,%2,%3}, {%4,%5,%6,%7}, {%8,%9}, {%0,%1,%2,%3};"
        : "+f"(c[0]), "+f"(c[1]), "+f"(c[2]), "+f"(c[3])
        : "r"(a[0]), "r"(a[1]), "r"(a[2]), "r"(a[3]),
          "r"(b[0]), "r"(b[1]));
}

__device__ __forceinline__ unsigned smem_u32(const void* p) {
    unsigned r;
    asm("{.reg .u64 t; cvta.to.shared.u64 t, %1; cvt.u32.u64 %0, t;}" : "=r"(r) : "l"(p));
    return r;
}

__device__ __forceinline__ void ldsm_x4(unsigned r[4], unsigned addr) {
    asm volatile("ldmatrix.sync.aligned.m8n8.x4.shared.b16 {%0,%1,%2,%3}, [%4];"
                 : "=r"(r[0]), "=r"(r[1]), "=r"(r[2]), "=r"(r[3]) : "r"(addr));
}

__device__ __forceinline__ void cp_async16(unsigned dst, const void* src) {
    asm volatile("cp.async.cg.shared.global [%0], [%1], 16;" :: "r"(dst), "l"(src));
}
__device__ __forceinline__ void cp_commit() { asm volatile("cp.async.commit_group;"); }
template <int N>
__device__ __forceinline__ void cp_wait() {
    asm volatile("cp.async.wait_group %0;" :: "n"(N));
}

__device__ __forceinline__ float fsigmoid(float x) { return 1.f / (1.f + __expf(-x)); }
__device__ __forceinline__ float ftanh(float x)    { return 2.f / (1.f + __expf(-2.f * x)) - 1.f; }

__device__ __forceinline__ void bar_step(int grp, int slot) {
    __syncthreads();
    if (threadIdx.x == 0) {
        unsigned* a = &g_cnt[grp * (TLEN + 1) + slot];
        asm volatile("red.release.gpu.global.add.u32 [%0], 1;" :: "l"(a) : "memory");
        unsigned v;
        do {
            asm volatile("ld.acquire.gpu.global.u32 %0, [%1];" : "=r"(v) : "l"(a) : "memory");
        } while (v < 64u);
    }
    __syncthreads();
}

// merged: bias sum + barrier-counter reset + W_ih bf16 conversion
__global__ void prep_kernel(const float* __restrict__ b_ih,
                            const float* __restrict__ b_hh,
                            const float* __restrict__ W) {
    int i = blockIdx.x * blockDim.x + threadIdx.x;
    if (i < GDIM) g_bias[i] = b_ih[i] + b_hh[i];
    if (i < 2 * (TLEN + 1)) g_cnt[i] = 0;
    size_t j = (size_t)i * 4;
    if (j < (size_t)GDIM * IDIM) {
        float4 t = *reinterpret_cast<const float4*>(&W[j]);
        __nv_bfloat162 p0 = __floats2bfloat162_rn(t.x, t.y);
        __nv_bfloat162 p1 = __floats2bfloat162_rn(t.z, t.w);
        *reinterpret_cast<__nv_bfloat162*>(&g_wihb[j])     = p0;
        *reinterpret_cast<__nv_bfloat162*>(&g_wihb[j + 2]) = p1;
    }
}

// x [B, I, T] -> g_xtb [(t*B+b)][i]  (bf16)
__global__ void transpose_x_kernel(const float* __restrict__ x) {
    __shared__ float tile[32][33];
    int b = blockIdx.z, i0 = blockIdx.x * 32, t0 = blockIdx.y * 32;
    int tx = threadIdx.x, ty = threadIdx.y;
#pragma unroll
    for (int r = 0; r < 32; r += 8)
        tile[ty + r][tx] = x[((size_t)b * IDIM + (i0 + ty + r)) * TLEN + (t0 + tx)];
    __syncthreads();
#pragma unroll
    for (int r = 0; r < 32; r += 8)
        g_xtb[((size_t)((t0 + ty + r) * BATCH + b)) * IDIM + (i0 + tx)] =
            __float2bfloat16(tile[tx][ty + r]);
}

// ---------- 2-stage pipelined bf16 GEMM (x_proj): 128x128, k-chunk 64 ------
__global__ __launch_bounds__(256) void gemm_bf16_tn(
    const __nv_bfloat16* __restrict__ A, const __nv_bfloat16* __restrict__ Bm,
    const float* __restrict__ bias, float* __restrict__ C,
    int M, int N, int K)
{
    extern __shared__ __align__(16) unsigned char sm[];
    unsigned smb = smem_u32(sm);
    float* bs = reinterpret_cast<float*>(sm + X_BS_OFF);
    int tid = threadIdx.x, lane = tid & 31, w = tid >> 5;
    int mt = w & 3, nh = w >> 2;
    int n0 = blockIdx.x * 128, m0 = blockIdx.y * 128;
    if (tid < 128) bs[tid] = bias[n0 + tid];

    float acc[2][8][4];
#pragma unroll
    for (int i = 0; i < 2; i++)
#pragma unroll
        for (int j = 0; j < 8; j++)
#pragma unroll
            for (int q = 0; q < 4; q++) acc[i][j][q] = 0.f;

    unsigned a_frag = smb + (32 * mt + (lane & 7) + ((lane >> 3) & 1) * 8) * 144
                      + ((lane >> 4) & 1) * 16;
    unsigned b_frag = smb + 2 * XA_STAGE
                      + (nh * 64 + ((lane >> 4) & 1) * 8 + (lane & 7)) * 144
                      + ((lane >> 3) & 1) * 16;

#define XSTAGE(kb, s) do {                                                        \
    unsigned ab = smb + (s) * XA_STAGE;                                           \
    _Pragma("unroll")                                                             \
    for (int j = 0; j < 4; j++) {                                                 \
        int v = tid + j * 256, row = v >> 3, c8 = (v & 7) * 8;                    \
        cp_async16(ab + row * 144 + c8 * 2, &A[(size_t)(m0 + row) * K + (kb) + c8]); \
    }                                                                             \
    unsigned bb = smb + 2 * XA_STAGE + (s) * XB_STAGE;                            \
    _Pragma("unroll")                                                             \
    for (int j = 0; j < 4; j++) {                                                 \
        int v = tid + j * 256, row = v >> 3, c8 = (v & 7) * 8;                    \
        cp_async16(bb + row * 144 + c8 * 2, &Bm[(size_t)(n0 + row) * K + (kb) + c8]); \
    }                                                                             \
    cp_commit(); } while (0)

    int nk = K / 64;
    XSTAGE(0, 0);
    for (int kc = 0; kc < nk; kc++) {
        if (kc + 1 < nk) XSTAGE((kc + 1) * 64, (kc + 1) & 1);
        cp_wait<1>();
        __syncthreads();
        unsigned soA = (unsigned)((kc & 1) * XA_STAGE);
        unsigned soB = (unsigned)((kc & 1) * XB_STAGE);
#pragma unroll
        for (int kt = 0; kt < 4; kt++) {
            unsigned a0[4], a1[4];
            ldsm_x4(a0, a_frag + soA + kt * 32);
            ldsm_x4(a1, a_frag + soA + 16 * 144 + kt * 32);
#pragma unroll
            for (int s = 0; s < 4; s++) {
                unsigned b0[4];
                ldsm_x4(b0, b_frag + soB + s * (16 * 144) + kt * 32);
                mma_bf16(acc[0][s * 2],     a0, &b0[0]);
                mma_bf16(acc[0][s * 2 + 1], a0, &b0[2]);
                mma_bf16(acc[1][s * 2],     a1, &b0[0]);
                mma_bf16(acc[1][s * 2 + 1], a1, &b0[2]);
            }
        }
        __syncthreads();
    }
#undef XSTAGE
    int g = lane >> 2, tg = lane & 3;
#pragma unroll
    for (int mi = 0; mi < 2; mi++) {
        int r0 = m0 + 32 * mt + 16 * mi + g;
#pragma unroll
        for (int nt = 0; nt < 8; nt++) {
            int cl = nh * 64 + nt * 8 + 2 * tg;
            C[(size_t)r0 * N + n0 + cl]           = acc[mi][nt][0] + bs[cl];
            C[(size_t)r0 * N + n0 + cl + 1]       = acc[mi][nt][1] + bs[cl + 1];
            C[(size_t)(r0 + 8) * N + n0 + cl]     = acc[mi][nt][2] + bs[cl];
            C[(size_t)(r0 + 8) * N + n0 + cl + 1] = acc[mi][nt][3] + bs[cl + 1];
        }
    }
}

// ---------- 2-stage pipelined tf32 GEMM (head): 128x128, k-chunk 32 --------
__global__ __launch_bounds__(256) void gemm_tn_kernel(
    const float* __restrict__ A, const float* __restrict__ Bm,
    const float* __restrict__ bias, float* __restrict__ C,
    int M, int N, int K)
{
    extern __shared__ __align__(16) unsigned char sm[];
    unsigned smb = smem_u32(sm);
    float* AsD = reinterpret_cast<float*>(sm);
    float* BsD = reinterpret_cast<float*>(sm + 2 * GA_STAGE);
    float* bs = reinterpret_cast<float*>(sm + G_BS_OFF);
    int tid = threadIdx.x;
    int w = tid >> 5, lane = tid & 31, g = lane >> 2, tg = lane & 3;
    int n0 = blockIdx.x * 128, m0 = blockIdx.y * 128;
    if (tid < 128) bs[tid] = bias[n0 + tid];

    float acc[16][4];
#pragma unroll
    for (int i = 0; i < 16; i++)
#pragma unroll
        for (int j = 0; j < 4; j++) acc[i][j] = 0.f;

#define HSTAGE(kb, s) do {                                                        \
    unsigned ab = smb + (s) * GA_STAGE;                                           \
    _Pragma("unroll")                                                             \
    for (int j = 0; j < 4; j++) {                                                 \
        int v = tid + j * 256, row = v >> 3, kq = (v & 7) * 4;                    \
        cp_async16(ab + row * 144 + kq * 4, &A[(size_t)(m0 + row) * K + (kb) + kq]); \
    }                                                                             \
    unsigned bb = smb + 2 * GA_STAGE + (s) * GB_STAGE;                            \
    _Pragma("unroll")                                                             \
    for (int j = 0; j < 4; j++) {                                                 \
        int v = tid + j * 256, row = v >> 3, kq = (v & 7) * 4;                    \
        cp_async16(bb + row * 144 + kq * 4, &Bm[(size_t)(n0 + row) * K + (kb) + kq]); \
    }                                                                             \
    cp_commit(); } while (0)

    int nk = K / 32;
    HSTAGE(0, 0);
    for (int kc = 0; kc < nk; kc++) {
        if (kc + 1 < nk) HSTAGE((kc + 1) * 32, (kc + 1) & 1);
        cp_wait<1>();
        __syncthreads();
        const float* As = AsD + (kc & 1) * (GA_STAGE / 4);
        const float* Bs = BsD + (kc & 1) * (GB_STAGE / 4);
#pragma unroll
        for (int s = 0; s < 4; s++) {
            int k = s * 8;
            float a[4];
            a[0] = to_tf32(As[(16 * w + g) * 36 + k + tg]);
            a[1] = to_tf32(As[(16 * w + 8 + g) * 36 + k + tg]);
            a[2] = to_tf32(As[(16 * w + g) * 36 + k + tg + 4]);
            a[3] = to_tf32(As[(16 * w + 8 + g) * 36 + k + tg + 4]);
#pragma unroll
            for (int nt = 0; nt < 16; nt++) {
                float bf[2];
                bf[0] = to_tf32(Bs[(8 * nt + g) * 36 + k + tg]);
                bf[1] = to_tf32(Bs[(8 * nt + g) * 36 + k + tg + 4]);
                mma_tf32(acc[nt], a, bf);
            }
        }
        __syncthreads();
    }
#undef HSTAGE
    int r0 = m0 + 16 * w + g;
#pragma unroll
    for (int nt = 0; nt < 16; nt++) {
        int cl = 8 * nt + 2 * tg;
        C[(size_t)r0 * N + n0 + cl]           = acc[nt][0] + bs[cl];
        C[(size_t)r0 * N + n0 + cl + 1]       = acc[nt][1] + bs[cl + 1];
        C[(size_t)(r0 + 8) * N + n0 + cl]     = acc[nt][2] + bs[cl];
        C[(size_t)(r0 + 8) * N + n0 + cl + 1] = acc[nt][3] + bs[cl + 1];
    }
}

// ---------------- persistent bf16 recurrence, 512 threads (16 warps) -------
// warp w: kh = w&3 (K quarter), sub = w>>2: nh = sub&1 (col half),
// mt = sub>>1 (16-row half). Each warp: 16 rows x 32 cols x 256 K.
__global__ __launch_bounds__(512, 1) void lstm_kernel(
    const float* __restrict__ W_hh,
    const float* __restrict__ h0,
    const float* __restrict__ c0)
{
    extern __shared__ __align__(16) unsigned char smraw[];
    __nv_bfloat16* Ws = reinterpret_cast<__nv_bfloat16*>(smraw + SM_WS);
    float* Gs = reinterpret_cast<float*>(smraw + SM_GS);   // [4][32][68]
    float* cs = reinterpret_cast<float*>(smraw + SM_CS);   // [32][16]

    int tid = threadIdx.x, lane = tid & 31, w = tid >> 5;
    int kh = w & 3, sub = w >> 2;
    int nh = sub & 1, mt = sub >> 1;
    int cb = blockIdx.x, grp = cb >> 6, cc = cb & 63;
    int j0 = cc * 16, bg0 = grp * BG;

    for (int idx = tid; idx < 64 * 256; idx += 512) {
        int cl = idx >> 8, kq = (idx & 255) * 4;
        int q = cl >> 4, jj = cl & 15;
        float4 t4 = *reinterpret_cast<const float4*>(
            &W_hh[(size_t)(q * HDIM + j0 + jj) * HDIM + kq]);
        __nv_bfloat16* d = &Ws[cl * HPAD + kq];
        d[0] = __float2bfloat16(t4.x); d[1] = __float2bfloat16(t4.y);
        d[2] = __float2bfloat16(t4.z); d[3] = __float2bfloat16(t4.w);
    }
    if (tid < BG * 16) {
        int b = tid >> 4, jj = tid & 15;
        cs[b * 16 + jj] = c0[j0 + jj];
        g_hb[0][(bg0 + b) * HDIM + j0 + jj] = __float2bfloat16(h0[j0 + jj]);
    }
    bar_step(grp, TLEN);

    unsigned AbufB = smem_u32(smraw + SM_ABUF) + kh * 13824;   // 3 bufs x 4608
    unsigned a_off = (16 * mt + (lane & 15)) * 144 + ((lane >> 4) & 1) * 16;
    unsigned b_base = smem_u32(Ws)
        + (nh * 32 + ((lane >> 4) & 1) * 8 + (lane & 7)) * (HPAD * 2)
        + ((lane >> 3) & 1) * 16 + kh * 512;
    unsigned b_base2 = b_base + 16 * HPAD * 2;

#define BARKH() asm volatile("bar.sync %0, 128;" :: "r"(1 + kh) : "memory")

#define LOADXG(tt, dst) do {                                                      \
    int b = tid >> 4, jj = tid & 15;                                              \
    const float* xp = &g_xproj[(size_t)((tt) * BATCH + bg0 + b) * GDIM + j0 + jj]; \
    dst[0] = xp[0];                                                               \
    dst[1] = xp[HDIM];                                                            \
    dst[2] = xp[2 * HDIM];                                                        \
    dst[3] = xp[3 * HDIM];                                                        \
} while (0)

// warp stages rows [sub*8, sub*8+8) of the 32-row chunk
#define STAGE(c, bi) do {                                                         \
    const __nv_bfloat16* hsrc = g_hb[p] + (size_t)(bg0 + sub * 8) * HDIM          \
                                + kh * 256 + (c) * 64;                            \
    _Pragma("unroll")                                                             \
    for (int it = 0; it < 2; it++) {                                              \
        int idx = it * 32 + lane;                                                 \
        int rw = idx >> 3, g16 = idx & 7;                                         \
        cp_async16(AbufB + (bi) * 4608 + (sub * 8 + rw) * 144 + g16 * 16,         \
                   hsrc + (size_t)rw * HDIM + g16 * 8);                           \
    }                                                                             \
    cp_commit(); } while (0)

#define COMPUTE(c, bi) do {                                                       \
    unsigned ab = AbufB + (bi) * 4608 + a_off;                                    \
    unsigned kb = (c) * 128;                                                      \
    _Pragma("unroll")                                                             \
    for (int kt = 0; kt < 4; kt++) {                                              \
        unsigned a0[4], b0[4], b1[4];                                             \
        ldsm_x4(a0, ab + kt * 32);                                                \
        ldsm_x4(b0, b_base + kb + kt * 32);                                       \
        ldsm_x4(b1, b_base2 + kb + kt * 32);                                      \
        mma_bf16(acc[0], a0, &b0[0]); mma_bf16(acc[1], a0, &b0[2]);               \
        mma_bf16(acc[2], a0, &b1[0]); mma_bf16(acc[3], a0, &b1[2]);               \
    } } while (0)

    float xg[4];
    LOADXG(0, xg);

    int p = 0;
    for (int t = 0; t < TLEN; t++) {
        float acc[4][4];
#pragma unroll
        for (int i = 0; i < 4; i++)
#pragma unroll
            for (int j = 0; j < 4; j++) acc[i][j] = 0.f;

        STAGE(0, 0);
        STAGE(1, 1);
        cp_wait<1>(); BARKH();
        COMPUTE(0, 0);
        STAGE(2, 2);
        cp_wait<1>(); BARKH();
        COMPUTE(1, 1);
        STAGE(3, 0);
        cp_wait<1>(); BARKH();
        COMPUTE(2, 2);
        cp_wait<0>(); BARKH();
        COMPUTE(3, 0);

        {
            int g = lane >> 2, tg = lane & 3;
            float* Gp = Gs + kh * (32 * 68);
            int r = 16 * mt + g;
#pragma unroll
            for (int nt = 0; nt < 4; nt++) {
                int cl = nh * 32 + nt * 8 + 2 * tg;
                Gp[r * 68 + cl]           = acc[nt][0];
                Gp[r * 68 + cl + 1]       = acc[nt][1];
                Gp[(r + 8) * 68 + cl]     = acc[nt][2];
                Gp[(r + 8) * 68 + cl + 1] = acc[nt][3];
            }
        }
        __syncthreads();

        float xgn[4];
        {
            int tn = (t + 1 < TLEN) ? t + 1 : t;
            LOADXG(tn, xgn);
        }

        // gate math: one (b, jj) item per thread
        float cn_r;
        {
            int b = tid >> 4, jj = tid & 15;
            const float* G0 = Gs + b * 68;
            const float* G1 = G0 + 32 * 68;
            const float* G2 = G1 + 32 * 68;
            const float* G3 = G2 + 32 * 68;
            float gi = xg[0] + (G0[jj]      + G1[jj])      + (G2[jj]      + G3[jj]);
            float gf = xg[1] + (G0[16 + jj] + G1[16 + jj]) + (G2[16 + jj] + G3[16 + jj]);
            float gg = xg[2] + (G0[32 + jj] + G1[32 + jj]) + (G2[32 + jj] + G3[32 + jj]);
            float go = xg[3] + (G0[48 + jj] + G1[48 + jj]) + (G2[48 + jj] + G3[48 + jj]);
            float ig = fsigmoid(gi);
            float fg = fsigmoid(gf);
            float gt = ftanh(gg);
            float og = fsigmoid(go);
            float cn = fg * cs[b * 16 + jj] + ig * gt;
            cs[b * 16 + jj] = cn;
            cn_r = cn;
            g_hb[p ^ 1][(bg0 + b) * HDIM + j0 + jj] = __float2bfloat16(og * ftanh(cn));
        }

        if (t != TLEN - 1) {
            __syncthreads();
            unsigned* a = &g_cnt[grp * (TLEN + 1) + t];
            if (tid == 0)
                asm volatile("red.release.gpu.global.add.u32 [%0], 1;" :: "l"(a) : "memory");
            {
                int b = tid >> 4, jj = tid & 15;
                g_chist[(size_t)(t * BATCH + bg0 + b) * HDIM + j0 + jj] = cn_r;
            }
            if (tid == 0) {
                unsigned v;
                do {
                    asm volatile("ld.acquire.gpu.global.u32 %0, [%1];"
                                 : "=r"(v) : "l"(a) : "memory");
                } while (v < 64u);
            }
            __syncthreads();
        } else {
            int b = tid >> 4, jj = tid & 15;
            g_chist[(size_t)(t * BATCH + bg0 + b) * HDIM + j0 + jj] = cn_r;
        }
        p ^= 1;
#pragma unroll
        for (int q = 0; q < 4; q++) xg[q] = xgn[q];
    }
#undef BARKH
#undef LOADXG
#undef STAGE
#undef COMPUTE
}

// row softmax with warp-shuffle reductions: P[16384][512] -> out
__global__ __launch_bounds__(128) void softmax_kernel(const float* __restrict__ P,
                                                      float* __restrict__ out) {
    __shared__ float wred[4];
    int r = blockIdx.x, tid = threadIdx.x, lane = tid & 31, w = tid >> 5;
    const float* row = &P[(size_t)r * ODIM];
    float4 v = *reinterpret_cast<const float4*>(&row[tid * 4]);
    float m = fmaxf(fmaxf(v.x, v.y), fmaxf(v.z, v.w));
#pragma unroll
    for (int s = 16; s > 0; s >>= 1)
        m = fmaxf(m, __shfl_xor_sync(0xFFFFFFFFu, m, s));
    if (lane == 0) wred[w] = m;
    __syncthreads();
    m = fmaxf(fmaxf(wred[0], wred[1]), fmaxf(wred[2], wred[3]));
    float e0 = expf(v.x - m), e1 = expf(v.y - m), e2 = expf(v.z - m), e3 = expf(v.w - m);
    float s = e0 + e1 + e2 + e3;
#pragma unroll
    for (int q = 16; q > 0; q >>= 1)
        s += __shfl_xor_sync(0xFFFFFFFFu, s, q);
    __syncthreads();
    if (lane == 0) wred[w] = s;
    __syncthreads();
    float inv = 1.f / (wred[0] + wred[1] + wred[2] + wred[3]);
    float4 o = make_float4(e0 * inv, e1 * inv, e2 * inv, e3 * inv);
    *reinterpret_cast<float4*>(&out[(size_t)r * ODIM + tid * 4]) = o;
}

extern "C" void kernel_launch(void* const* d_in, const int* in_sizes, int n_in,
                              void* d_out, int out_size) {
    const float* x     = (const float*)d_in[0];
    const float* W_ih  = (const float*)d_in[1];
    const float* W_hh  = (const float*)d_in[2];
    const float* b_ih  = (const float*)d_in[3];
    const float* b_hh  = (const float*)d_in[4];
    const float* W_out = (const float*)d_in[5];
    const float* b_out = (const float*)d_in[6];
    const float* h0    = (const float*)d_in[7];
    const float* c0    = (const float*)d_in[8];
    float* out = (float*)d_out;
    (void)in_sizes; (void)n_in; (void)out_size;

    cudaFuncSetAttribute(lstm_kernel, cudaFuncAttributeMaxDynamicSharedMemorySize,
                         (int)LSTM_SMEM);
    cudaFuncSetAttribute(gemm_bf16_tn, cudaFuncAttributeMaxDynamicSharedMemorySize,
                         (int)XGEMM_SMEM);
    cudaFuncSetAttribute(gemm_tn_kernel, cudaFuncAttributeMaxDynamicSharedMemorySize,
                         (int)GEMM_SMEM);

    prep_kernel<<<(GDIM * IDIM / 4 + 255) / 256, 256>>>(b_ih, b_hh, W_ih);
    transpose_x_kernel<<<dim3(IDIM / 32, TLEN / 32, BATCH), dim3(32, 8)>>>(x);

    {
        __nv_bfloat16 *A, *B; float *C, *bias;
        cudaGetSymbolAddress((void**)&A, g_xtb);
        cudaGetSymbolAddress((void**)&B, g_wihb);
        cudaGetSymbolAddress((void**)&C, g_xproj);
        cudaGetSymbolAddress((void**)&bias, g_bias);
        gemm_bf16_tn<<<dim3(GDIM / 128, M1 / 128), 256, XGEMM_SMEM>>>(
            A, B, bias, C, M1, GDIM, IDIM);
    }

    lstm_kernel<<<NCTA, 512, LSTM_SMEM>>>(W_hh, h0, c0);

    {
        float *A, *C;
        cudaGetSymbolAddress((void**)&A, g_chist);
        cudaGetSymbolAddress((void**)&C, g_xt);
        gemm_tn_kernel<<<dim3(ODIM / 128, M1 / 128), 256, GEMM_SMEM>>>(
            A, W_out, b_out, C, M1, ODIM, HDIM);
        softmax_kernel<<<M1, 128>>>(C, out);
    }
}

// round 17
// speedup vs baseline: 1.0570x; 1.0570x over previous
#include <cuda_runtime.h>
#include <cuda_bf16.h>
#include <cstdint>
#include <cstddef>
#include <math.h>

#define BATCH 64
#define IDIM  512
#define HDIM  1024
#define GDIM  4096
#define TLEN  256
#define ODIM  512
#define M1    (TLEN*BATCH)
#define NCTA  128
#define BG    32
#define HPAD  1032

// lstm SMEM byte offsets (triple-buffered A chunks)
#define SM_WS    0                         // 64*HPAD*2 = 132096
#define SM_ABUF  132096                    // 4 kh * 3 bufs * 4608B = 55296
#define SM_GS    (132096 + 55296)          // Gs [4][32][68] f32 = 34816
#define SM_CS    (SM_GS + 34816)           // cs [32][16] f32
#define LSTM_SMEM (SM_CS + 2048)           // 224256

// 2-stage pipelined bf16 GEMM (x_proj, 128x128)
#define XA_STAGE 18432
#define XB_STAGE 18432
#define X_BS_OFF (2*XA_STAGE + 2*XB_STAGE)
#define XGEMM_SMEM (X_BS_OFF + 512)

// 2-stage pipelined tf32 GEMM (head, 128x128)
#define GA_STAGE 18432
#define GB_STAGE 18432
#define G_BS_OFF (2*GA_STAGE + 2*GB_STAGE)
#define GEMM_SMEM (G_BS_OFF + 512)

__device__ float g_xt[(size_t)M1 * ODIM];
__device__ __nv_bfloat16 g_xtb[(size_t)M1 * IDIM];
__device__ __nv_bfloat16 g_wihb[(size_t)GDIM * IDIM];
__device__ float g_xproj[(size_t)M1 * GDIM];
__device__ float g_chist[(size_t)M1 * HDIM];
__device__ __nv_bfloat16 g_hb[2][BATCH * HDIM];
__device__ float g_bias[GDIM];
__device__ unsigned g_cnt[2 * (TLEN + 1)];

__device__ __forceinline__ float to_tf32(float x) {
    unsigned u; asm("cvt.rna.tf32.f32 %0, %1;" : "=r"(u) : "f"(x));
    return __uint_as_float(u);
}

__device__ __forceinline__ void mma_tf32(float c[4], const float a[4], const float b[2]) {
    asm volatile(
        "mma.sync.aligned.m16n8k8.row.col.f32.tf32.tf32.f32 "
        "{%0,%1,%2,%3}, {%4,%5,%6,%7}, {%8,%9}, {%0,%1,%2,%3};"
        : "+f"(c[0]), "+f"(c[1]), "+f"(c[2]), "+f"(c[3])
        : "r"(__float_as_uint(a[0])), "r"(__float_as_uint(a[1])),
          "r"(__float_as_uint(a[2])), "r"(__float_as_uint(a[3])),
          "r"(__float_as_uint(b[0])), "r"(__float_as_uint(b[1])));
}

__device__ __forceinline__ void mma_bf16(float c[4], const unsigned a[4], const unsigned b[2]) {
    asm volatile(
        "mma.sync.aligned.m16n8k16.row.col.f32.bf16.bf16.f32 "
        "{%0,%1,%2,%3}, {%4,%5,%6,%7}, {%8,%9}, {%0,%1,%2,%3};"
        : "+f"(c[0]), "+f"(c[1]), "+f"(c[2]), "+f"(c[3])
        : "r"(a[0]), "r"(a[1]), "r"(a[2]), "r"(a[3]),
          "r"(b[0]), "r"(b[1]));
}

__device__ __forceinline__ unsigned smem_u32(const void* p) {
    unsigned r;
    asm("{.reg .u64 t; cvta.to.shared.u64 t, %1; cvt.u32.u64 %0, t;}" : "=r"(r) : "l"(p));
    return r;
}

__device__ __forceinline__ void ldsm_x4(unsigned r[4], unsigned addr) {
    asm volatile("ldmatrix.sync.aligned.m8n8.x4.shared.b16 {%0,%1,%2,%3}, [%4];"
                 : "=r"(r[0]), "=r"(r[1]), "=r"(r[2]), "=r"(r[3]) : "r"(addr));
}

__device__ __forceinline__ void cp_async16(unsigned dst, const void* src) {
    asm volatile("cp.async.cg.shared.global [%0], [%1], 16;" :: "r"(dst), "l"(src));
}
__device__ __forceinline__ void cp_commit() { asm volatile("cp.async.commit_group;"); }
template <int N>
__device__ __forceinline__ void cp_wait() {
    asm volatile("cp.async.wait_group %0;" :: "n"(N));
}

__device__ __forceinline__ void stg_cs(float* p, float v) {
    asm volatile("st.global.cs.f32 [%0], %1;" :: "l"(p), "f"(v) : "memory");
}

__device__ __forceinline__ float fsigmoid(float x) { return 1.f / (1.f + __expf(-x)); }
__device__ __forceinline__ float ftanh(float x)    { return 2.f / (1.f + __expf(-2.f * x)) - 1.f; }

__device__ __forceinline__ void bar_step(int grp, int slot) {
    __syncthreads();
    if (threadIdx.x == 0) {
        unsigned* a = &g_cnt[grp * (TLEN + 1) + slot];
        asm volatile("red.release.gpu.global.add.u32 [%0], 1;" :: "l"(a) : "memory");
        unsigned v;
        do {
            asm volatile("ld.acquire.gpu.global.u32 %0, [%1];" : "=r"(v) : "l"(a) : "memory");
        } while (v < 64u);
    }
    __syncthreads();
}

// merged: bias sum + barrier-counter reset + W_ih bf16 conversion
__global__ void prep_kernel(const float* __restrict__ b_ih,
                            const float* __restrict__ b_hh,
                            const float* __restrict__ W) {
    int i = blockIdx.x * blockDim.x + threadIdx.x;
    if (i < GDIM) g_bias[i] = b_ih[i] + b_hh[i];
    if (i < 2 * (TLEN + 1)) g_cnt[i] = 0;
    size_t j = (size_t)i * 4;
    if (j < (size_t)GDIM * IDIM) {
        float4 t = *reinterpret_cast<const float4*>(&W[j]);
        __nv_bfloat162 p0 = __floats2bfloat162_rn(t.x, t.y);
        __nv_bfloat162 p1 = __floats2bfloat162_rn(t.z, t.w);
        *reinterpret_cast<__nv_bfloat162*>(&g_wihb[j])     = p0;
        *reinterpret_cast<__nv_bfloat162*>(&g_wihb[j + 2]) = p1;
    }
}

// x [B, I, T] -> g_xtb [(t*B+b)][i]  (bf16)
__global__ void transpose_x_kernel(const float* __restrict__ x) {
    __shared__ float tile[32][33];
    int b = blockIdx.z, i0 = blockIdx.x * 32, t0 = blockIdx.y * 32;
    int tx = threadIdx.x, ty = threadIdx.y;
#pragma unroll
    for (int r = 0; r < 32; r += 8)
        tile[ty + r][tx] = x[((size_t)b * IDIM + (i0 + ty + r)) * TLEN + (t0 + tx)];
    __syncthreads();
#pragma unroll
    for (int r = 0; r < 32; r += 8)
        g_xtb[((size_t)((t0 + ty + r) * BATCH + b)) * IDIM + (i0 + tx)] =
            __float2bfloat16(tile[tx][ty + r]);
}

// ---------- 2-stage pipelined bf16 GEMM (x_proj): 128x128, k-chunk 64 ------
__global__ __launch_bounds__(256) void gemm_bf16_tn(
    const __nv_bfloat16* __restrict__ A, const __nv_bfloat16* __restrict__ Bm,
    const float* __restrict__ bias, float* __restrict__ C,
    int M, int N, int K)
{
    extern __shared__ __align__(16) unsigned char sm[];
    unsigned smb = smem_u32(sm);
    float* bs = reinterpret_cast<float*>(sm + X_BS_OFF);
    int tid = threadIdx.x, lane = tid & 31, w = tid >> 5;
    int mt = w & 3, nh = w >> 2;
    int n0 = blockIdx.x * 128, m0 = blockIdx.y * 128;
    if (tid < 128) bs[tid] = bias[n0 + tid];

    float acc[2][8][4];
#pragma unroll
    for (int i = 0; i < 2; i++)
#pragma unroll
        for (int j = 0; j < 8; j++)
#pragma unroll
            for (int q = 0; q < 4; q++) acc[i][j][q] = 0.f;

    unsigned a_frag = smb + (32 * mt + (lane & 7) + ((lane >> 3) & 1) * 8) * 144
                      + ((lane >> 4) & 1) * 16;
    unsigned b_frag = smb + 2 * XA_STAGE
                      + (nh * 64 + ((lane >> 4) & 1) * 8 + (lane & 7)) * 144
                      + ((lane >> 3) & 1) * 16;

#define XSTAGE(kb, s) do {                                                        \
    unsigned ab = smb + (s) * XA_STAGE;                                           \
    _Pragma("unroll")                                                             \
    for (int j = 0; j < 4; j++) {                                                 \
        int v = tid + j * 256, row = v >> 3, c8 = (v & 7) * 8;                    \
        cp_async16(ab + row * 144 + c8 * 2, &A[(size_t)(m0 + row) * K + (kb) + c8]); \
    }                                                                             \
    unsigned bb = smb + 2 * XA_STAGE + (s) * XB_STAGE;                            \
    _Pragma("unroll")                                                             \
    for (int j = 0; j < 4; j++) {                                                 \
        int v = tid + j * 256, row = v >> 3, c8 = (v & 7) * 8;                    \
        cp_async16(bb + row * 144 + c8 * 2, &Bm[(size_t)(n0 + row) * K + (kb) + c8]); \
    }                                                                             \
    cp_commit(); } while (0)

    int nk = K / 64;
    XSTAGE(0, 0);
    for (int kc = 0; kc < nk; kc++) {
        if (kc + 1 < nk) XSTAGE((kc + 1) * 64, (kc + 1) & 1);
        cp_wait<1>();
        __syncthreads();
        unsigned soA = (unsigned)((kc & 1) * XA_STAGE);
        unsigned soB = (unsigned)((kc & 1) * XB_STAGE);
#pragma unroll
        for (int kt = 0; kt < 4; kt++) {
            unsigned a0[4], a1[4];
            ldsm_x4(a0, a_frag + soA + kt * 32);
            ldsm_x4(a1, a_frag + soA + 16 * 144 + kt * 32);
#pragma unroll
            for (int s = 0; s < 4; s++) {
                unsigned b0[4];
                ldsm_x4(b0, b_frag + soB + s * (16 * 144) + kt * 32);
                mma_bf16(acc[0][s * 2],     a0, &b0[0]);
                mma_bf16(acc[0][s * 2 + 1], a0, &b0[2]);
                mma_bf16(acc[1][s * 2],     a1, &b0[0]);
                mma_bf16(acc[1][s * 2 + 1], a1, &b0[2]);
            }
        }
        __syncthreads();
    }
#undef XSTAGE
    int g = lane >> 2, tg = lane & 3;
#pragma unroll
    for (int mi = 0; mi < 2; mi++) {
        int r0 = m0 + 32 * mt + 16 * mi + g;
#pragma unroll
        for (int nt = 0; nt < 8; nt++) {
            int cl = nh * 64 + nt * 8 + 2 * tg;
            C[(size_t)r0 * N + n0 + cl]           = acc[mi][nt][0] + bs[cl];
            C[(size_t)r0 * N + n0 + cl + 1]       = acc[mi][nt][1] + bs[cl + 1];
            C[(size_t)(r0 + 8) * N + n0 + cl]     = acc[mi][nt][2] + bs[cl];
            C[(size_t)(r0 + 8) * N + n0 + cl + 1] = acc[mi][nt][3] + bs[cl + 1];
        }
    }
}

// ---------- 2-stage pipelined tf32 GEMM (head): 128x128, k-chunk 32 --------
__global__ __launch_bounds__(256) void gemm_tn_kernel(
    const float* __restrict__ A, const float* __restrict__ Bm,
    const float* __restrict__ bias, float* __restrict__ C,
    int M, int N, int K)
{
    extern __shared__ __align__(16) unsigned char sm[];
    unsigned smb = smem_u32(sm);
    float* AsD = reinterpret_cast<float*>(sm);
    float* BsD = reinterpret_cast<float*>(sm + 2 * GA_STAGE);
    float* bs = reinterpret_cast<float*>(sm + G_BS_OFF);
    int tid = threadIdx.x;
    int w = tid >> 5, lane = tid & 31, g = lane >> 2, tg = lane & 3;
    int n0 = blockIdx.x * 128, m0 = blockIdx.y * 128;
    if (tid < 128) bs[tid] = bias[n0 + tid];

    float acc[16][4];
#pragma unroll
    for (int i = 0; i < 16; i++)
#pragma unroll
        for (int j = 0; j < 4; j++) acc[i][j] = 0.f;

#define HSTAGE(kb, s) do {                                                        \
    unsigned ab = smb + (s) * GA_STAGE;                                           \
    _Pragma("unroll")                                                             \
    for (int j = 0; j < 4; j++) {                                                 \
        int v = tid + j * 256, row = v >> 3, kq = (v & 7) * 4;                    \
        cp_async16(ab + row * 144 + kq * 4, &A[(size_t)(m0 + row) * K + (kb) + kq]); \
    }                                                                             \
    unsigned bb = smb + 2 * GA_STAGE + (s) * GB_STAGE;                            \
    _Pragma("unroll")                                                             \
    for (int j = 0; j < 4; j++) {                                                 \
        int v = tid + j * 256, row = v >> 3, kq = (v & 7) * 4;                    \
        cp_async16(bb + row * 144 + kq * 4, &Bm[(size_t)(n0 + row) * K + (kb) + kq]); \
    }                                                                             \
    cp_commit(); } while (0)

    int nk = K / 32;
    HSTAGE(0, 0);
    for (int kc = 0; kc < nk; kc++) {
        if (kc + 1 < nk) HSTAGE((kc + 1) * 32, (kc + 1) & 1);
        cp_wait<1>();
        __syncthreads();
        const float* As = AsD + (kc & 1) * (GA_STAGE / 4);
        const float* Bs = BsD + (kc & 1) * (GB_STAGE / 4);
#pragma unroll
        for (int s = 0; s < 4; s++) {
            int k = s * 8;
            float a[4];
            a[0] = to_tf32(As[(16 * w + g) * 36 + k + tg]);
            a[1] = to_tf32(As[(16 * w + 8 + g) * 36 + k + tg]);
            a[2] = to_tf32(As[(16 * w + g) * 36 + k + tg + 4]);
            a[3] = to_tf32(As[(16 * w + 8 + g) * 36 + k + tg + 4]);
#pragma unroll
            for (int nt = 0; nt < 16; nt++) {
                float bf[2];
                bf[0] = to_tf32(Bs[(8 * nt + g) * 36 + k + tg]);
                bf[1] = to_tf32(Bs[(8 * nt + g) * 36 + k + tg + 4]);
                mma_tf32(acc[nt], a, bf);
            }
        }
        __syncthreads();
    }
#undef HSTAGE
    int r0 = m0 + 16 * w + g;
#pragma unroll
    for (int nt = 0; nt < 16; nt++) {
        int cl = 8 * nt + 2 * tg;
        stg_cs(&C[(size_t)r0 * N + n0 + cl],           acc[nt][0] + bs[cl]);
        stg_cs(&C[(size_t)r0 * N + n0 + cl + 1],       acc[nt][1] + bs[cl + 1]);
        stg_cs(&C[(size_t)(r0 + 8) * N + n0 + cl],     acc[nt][2] + bs[cl]);
        stg_cs(&C[(size_t)(r0 + 8) * N + n0 + cl + 1], acc[nt][3] + bs[cl + 1]);
    }
}

// ---------------- persistent bf16 recurrence (W fragments in registers) ----
__global__ __launch_bounds__(256, 1) void lstm_kernel(
    const float* __restrict__ W_hh,
    const float* __restrict__ h0,
    const float* __restrict__ c0)
{
    extern __shared__ __align__(16) unsigned char smraw[];
    __nv_bfloat16* Ws = reinterpret_cast<__nv_bfloat16*>(smraw + SM_WS);
    float* Gs = reinterpret_cast<float*>(smraw + SM_GS);
    float* cs = reinterpret_cast<float*>(smraw + SM_CS);

    int tid = threadIdx.x, lane = tid & 31, w = tid >> 5;
    int kh = w & 3, nh = w >> 2;
    int cb = blockIdx.x, grp = cb >> 6, cc = cb & 63;
    int j0 = cc * 16, bg0 = grp * BG;

    for (int idx = tid; idx < 64 * 256; idx += 256) {
        int cl = idx >> 8, kq = (idx & 255) * 4;
        int q = cl >> 4, jj = cl & 15;
        float4 t4 = *reinterpret_cast<const float4*>(
            &W_hh[(size_t)(q * HDIM + j0 + jj) * HDIM + kq]);
        __nv_bfloat16* d = &Ws[cl * HPAD + kq];
        d[0] = __float2bfloat16(t4.x); d[1] = __float2bfloat16(t4.y);
        d[2] = __float2bfloat16(t4.z); d[3] = __float2bfloat16(t4.w);
    }
    for (int i = tid; i < BG * 16; i += 256) {
        int b = i >> 4, jj = i & 15;
        cs[b * 16 + jj] = c0[j0 + jj];
        g_hb[0][(bg0 + b) * HDIM + j0 + jj] = __float2bfloat16(h0[j0 + jj]);
    }
    bar_step(grp, TLEN);

    unsigned AbufB = smem_u32(smraw + SM_ABUF) + kh * 13824;
    unsigned a_off = (lane & 15) * 144 + ((lane >> 4) & 1) * 16;
    unsigned b_base = smem_u32(Ws)
        + (nh * 32 + ((lane >> 4) & 1) * 8 + (lane & 7)) * (HPAD * 2)
        + ((lane >> 3) & 1) * 16 + kh * 512;
    unsigned b_base2 = b_base + 16 * HPAD * 2;

    unsigned wreg[4][4][8];
#pragma unroll
    for (int c = 0; c < 4; c++)
#pragma unroll
        for (int kt = 0; kt < 4; kt++) {
            ldsm_x4(&wreg[c][kt][0], b_base + c * 128 + kt * 32);
            ldsm_x4(&wreg[c][kt][4], b_base2 + c * 128 + kt * 32);
        }

#define BARKH() asm volatile("bar.sync %0, 64;" :: "r"(1 + kh) : "memory")

#define LOADXG(tt, dst) do {                                                      \
    _Pragma("unroll")                                                             \
    for (int u = 0; u < 2; u++) {                                                 \
        int it = tid + u * 256;                                                   \
        int b = it >> 4, jj = it & 15;                                            \
        const float* xp = &g_xproj[(size_t)((tt) * BATCH + bg0 + b) * GDIM + j0 + jj]; \
        dst[u][0] = xp[0];                                                        \
        dst[u][1] = xp[HDIM];                                                     \
        dst[u][2] = xp[2 * HDIM];                                                 \
        dst[u][3] = xp[3 * HDIM];                                                 \
    } } while (0)

#define STAGE(c, bi) do {                                                         \
    const __nv_bfloat16* hsrc = g_hb[p] + (size_t)(bg0 + nh * 16) * HDIM          \
                                + kh * 256 + (c) * 64;                            \
    _Pragma("unroll")                                                             \
    for (int it = 0; it < 4; it++) {                                              \
        int idx = it * 32 + lane;                                                 \
        int rw = idx >> 3, g16 = idx & 7;                                         \
        cp_async16(AbufB + (bi) * 4608 + (nh * 16 + rw) * 144 + g16 * 16,         \
                   hsrc + (size_t)rw * HDIM + g16 * 8);                           \
    }                                                                             \
    cp_commit(); } while (0)

#define COMPUTE(c, bi) do {                                                       \
    unsigned ab = AbufB + (bi) * 4608 + a_off;                                    \
    _Pragma("unroll")                                                             \
    for (int kt = 0; kt < 4; kt++) {                                              \
        unsigned a0[4], a1[4];                                                    \
        ldsm_x4(a0, ab + kt * 32);                                                \
        ldsm_x4(a1, ab + 16 * 144 + kt * 32);                                     \
        mma_bf16(acc[0][0], a0, &wreg[c][kt][0]);                                 \
        mma_bf16(acc[0][1], a0, &wreg[c][kt][2]);                                 \
        mma_bf16(acc[0][2], a0, &wreg[c][kt][4]);                                 \
        mma_bf16(acc[0][3], a0, &wreg[c][kt][6]);                                 \
        mma_bf16(acc[1][0], a1, &wreg[c][kt][0]);                                 \
        mma_bf16(acc[1][1], a1, &wreg[c][kt][2]);                                 \
        mma_bf16(acc[1][2], a1, &wreg[c][kt][4]);                                 \
        mma_bf16(acc[1][3], a1, &wreg[c][kt][6]);                                 \
    } } while (0)

    float xg[2][4];
    LOADXG(0, xg);

    int p = 0;
    for (int t = 0; t < TLEN; t++) {
        float acc[2][4][4];
#pragma unroll
        for (int i = 0; i < 2; i++)
#pragma unroll
            for (int j = 0; j < 4; j++)
#pragma unroll
                for (int q = 0; q < 4; q++) acc[i][j][q] = 0.f;

        STAGE(0, 0);
        STAGE(1, 1);
        cp_wait<1>(); BARKH();
        COMPUTE(0, 0);
        STAGE(2, 2);
        cp_wait<1>(); BARKH();
        COMPUTE(1, 1);
        STAGE(3, 0);
        cp_wait<1>(); BARKH();
        COMPUTE(2, 2);
        cp_wait<0>(); BARKH();
        COMPUTE(3, 0);

        {
            int g = lane >> 2, tg = lane & 3;
            float* Gp = Gs + kh * (32 * 68);
#pragma unroll
            for (int mi = 0; mi < 2; mi++) {
                int r = 16 * mi + g;
#pragma unroll
                for (int nt = 0; nt < 4; nt++) {
                    int cl = nh * 32 + nt * 8 + 2 * tg;
                    Gp[r * 68 + cl]           = acc[mi][nt][0];
                    Gp[r * 68 + cl + 1]       = acc[mi][nt][1];
                    Gp[(r + 8) * 68 + cl]     = acc[mi][nt][2];
                    Gp[(r + 8) * 68 + cl + 1] = acc[mi][nt][3];
                }
            }
        }
        __syncthreads();

        float xgn[2][4];
        {
            int tn = (t + 1 < TLEN) ? t + 1 : t;
            LOADXG(tn, xgn);
        }

        float cn_r[2];
#pragma unroll
        for (int u = 0; u < 2; u++) {
            int it = tid + u * 256;
            int b = it >> 4, jj = it & 15;
            const float* G0 = Gs + b * 68;
            const float* G1 = G0 + 32 * 68;
            const float* G2 = G1 + 32 * 68;
            const float* G3 = G2 + 32 * 68;
            float gi = xg[u][0] + (G0[jj]      + G1[jj])      + (G2[jj]      + G3[jj]);
            float gf = xg[u][1] + (G0[16 + jj] + G1[16 + jj]) + (G2[16 + jj] + G3[16 + jj]);
            float gg = xg[u][2] + (G0[32 + jj] + G1[32 + jj]) + (G2[32 + jj] + G3[32 + jj]);
            float go = xg[u][3] + (G0[48 + jj] + G1[48 + jj]) + (G2[48 + jj] + G3[48 + jj]);
            float ig = fsigmoid(gi);
            float fg = fsigmoid(gf);
            float gt = ftanh(gg);
            float og = fsigmoid(go);
            float cn = fg * cs[b * 16 + jj] + ig * gt;
            cs[b * 16 + jj] = cn;
            cn_r[u] = cn;
            g_hb[p ^ 1][(bg0 + b) * HDIM + j0 + jj] = __float2bfloat16(og * ftanh(cn));
        }

        if (t != TLEN - 1) {
            __syncthreads();
            unsigned* a = &g_cnt[grp * (TLEN + 1) + t];
            if (tid == 0)
                asm volatile("red.release.gpu.global.add.u32 [%0], 1;" :: "l"(a) : "memory");
#pragma unroll
            for (int u = 0; u < 2; u++) {
                int it = tid + u * 256;
                int b = it >> 4, jj = it & 15;
                g_chist[(size_t)(t * BATCH + bg0 + b) * HDIM + j0 + jj] = cn_r[u];
            }
            if (tid == 0) {
                unsigned v;
                do {
                    asm volatile("ld.acquire.gpu.global.u32 %0, [%1];"
                                 : "=r"(v) : "l"(a) : "memory");
                } while (v < 64u);
            }
            __syncthreads();
        } else {
#pragma unroll
            for (int u = 0; u < 2; u++) {
                int it = tid + u * 256;
                int b = it >> 4, jj = it & 15;
                g_chist[(size_t)(t * BATCH + bg0 + b) * HDIM + j0 + jj] = cn_r[u];
            }
        }
        p ^= 1;
#pragma unroll
        for (int u = 0; u < 2; u++)
#pragma unroll
            for (int q = 0; q < 4; q++) xg[u][q] = xgn[u][q];
    }
#undef BARKH
#undef LOADXG
#undef STAGE
#undef COMPUTE
}

// row softmax with warp-shuffle reductions: P[16384][512] -> out
__global__ __launch_bounds__(128) void softmax_kernel(const float* __restrict__ P,
                                                      float* __restrict__ out) {
    __shared__ float wred[4];
    int r = blockIdx.x, tid = threadIdx.x, lane = tid & 31, w = tid >> 5;
    const float* row = &P[(size_t)r * ODIM];
    float4 v = *reinterpret_cast<const float4*>(&row[tid * 4]);
    float m = fmaxf(fmaxf(v.x, v.y), fmaxf(v.z, v.w));
#pragma unroll
    for (int s = 16; s > 0; s >>= 1)
        m = fmaxf(m, __shfl_xor_sync(0xFFFFFFFFu, m, s));
    if (lane == 0) wred[w] = m;
    __syncthreads();
    m = fmaxf(fmaxf(wred[0], wred[1]), fmaxf(wred[2], wred[3]));
    float e0 = __expf(v.x - m), e1 = __expf(v.y - m);
    float e2 = __expf(v.z - m), e3 = __expf(v.w - m);
    float s = e0 + e1 + e2 + e3;
#pragma unroll
    for (int q = 16; q > 0; q >>= 1)
        s += __shfl_xor_sync(0xFFFFFFFFu, s, q);
    __syncthreads();
    if (lane == 0) wred[w] = s;
    __syncthreads();
    float inv = 1.f / (wred[0] + wred[1] + wred[2] + wred[3]);
    float4 o = make_float4(e0 * inv, e1 * inv, e2 * inv, e3 * inv);
    *reinterpret_cast<float4*>(&out[(size_t)r * ODIM + tid * 4]) = o;
}

extern "C" void kernel_launch(void* const* d_in, const int* in_sizes, int n_in,
                              void* d_out, int out_size) {
    const float* x     = (const float*)d_in[0];
    const float* W_ih  = (const float*)d_in[1];
    const float* W_hh  = (const float*)d_in[2];
    const float* b_ih  = (const float*)d_in[3];
    const float* b_hh  = (const float*)d_in[4];
    const float* W_out = (const float*)d_in[5];
    const float* b_out = (const float*)d_in[6];
    const float* h0    = (const float*)d_in[7];
    const float* c0    = (const float*)d_in[8];
    float* out = (float*)d_out;
    (void)in_sizes; (void)n_in; (void)out_size;

    cudaFuncSetAttribute(lstm_kernel, cudaFuncAttributeMaxDynamicSharedMemorySize,
                         (int)LSTM_SMEM);
    cudaFuncSetAttribute(gemm_bf16_tn, cudaFuncAttributeMaxDynamicSharedMemorySize,
                         (int)XGEMM_SMEM);
    cudaFuncSetAttribute(gemm_tn_kernel, cudaFuncAttributeMaxDynamicSharedMemorySize,
                         (int)GEMM_SMEM);

    prep_kernel<<<(GDIM * IDIM / 4 + 255) / 256, 256>>>(b_ih, b_hh, W_ih);
    transpose_x_kernel<<<dim3(IDIM / 32, TLEN / 32, BATCH), dim3(32, 8)>>>(x);

    {
        __nv_bfloat16 *A, *B; float *C, *bias;
        cudaGetSymbolAddress((void**)&A, g_xtb);
        cudaGetSymbolAddress((void**)&B, g_wihb);
        cudaGetSymbolAddress((void**)&C, g_xproj);
        cudaGetSymbolAddress((void**)&bias, g_bias);
        gemm_bf16_tn<<<dim3(GDIM / 128, M1 / 128), 256, XGEMM_SMEM>>>(
            A, B, bias, C, M1, GDIM, IDIM);
    }

    lstm_kernel<<<NCTA, 256, LSTM_SMEM>>>(W_hh, h0, c0);

    {
        float *A, *C;
        cudaGetSymbolAddress((void**)&A, g_chist);
        cudaGetSymbolAddress((void**)&C, g_xt);
        gemm_tn_kernel<<<dim3(ODIM / 128, M1 / 128), 256, GEMM_SMEM>>>(
            A, W_out, b_out, C, M1, ODIM, HDIM);
        softmax_kernel<<<M1, 128>>>(C, out);
    }
}